// round 6
// baseline (speedup 1.0000x reference)
#include <cuda_runtime.h>
#include <math.h>

#define BB   64
#define NPG  1024
#define NN   (BB * NPG)       // 65536 nodes
#define EE   (BB * 16384)     // 1048576 edges
#define EPG  16384            // edges per graph
#define INF  64
#define HIDF 128
#define OUTF 32

#define ADJ_ELEMS  ((size_t)BB * NPG * NPG)   // 67108864
#define MEAN_OFF   ADJ_ELEMS
#define LS_OFF     (ADJ_ELEMS + (size_t)NN * OUTF)

#define AGG_SMEM   (NPG * 32 * 4 + EPG * 4)   // 196608 B
// k_mlp dynamic smem: sH(128*132) + sA(32*132) + sW(32*128) + rs(128) + b1(128)
#define MLP_SMEM   ((128 * 132 + 32 * 132 + 32 * 128 + 256) * 4)   // 101888 B
// k_adj dynamic smem: sAdup(32*128 u64) + sB(32*132 f32)
#define ADJ_SMEM   (32 * 128 * 8 + 32 * 132 * 4)                   // 49664 B

// ---------------- scratch (static device globals; no runtime alloc) -------
__device__ float g_rs_out[NN];
__device__ float g_rs_in[NN];
__device__ int   g_rowptr[NN + 1];
__device__ int   g_csr[EE];        // pre-scaled LOCAL byte offsets (src*128)
__device__ float g_a[NN * INF];    // aggregated+scaled input features
__device__ float g_p[NN * 64];     // (h * rs_out) @ [W2 | W3]
__device__ float g_q[NN * 64];     // aggregated p (pre-bias mean|log_std)
__device__ float g_z[NN * OUTF];   // latent z

typedef unsigned long long u64;

// ---------------- f32x2 helpers (FFMA2) -----------------------------------
__device__ __forceinline__ u64 pack2(float lo, float hi) {
    u64 r;
    asm("mov.b64 %0, {%1, %2};" : "=l"(r) : "f"(lo), "f"(hi));
    return r;
}
__device__ __forceinline__ u64 fma2(u64 a, u64 b, u64 c) {
    u64 d;
    asm("fma.rn.f32x2 %0, %1, %2, %3;" : "=l"(d) : "l"(a), "l"(b), "l"(c));
    return d;
}
__device__ __forceinline__ void unpack2(u64 v, float& a, float& b) {
    asm("mov.b64 {%0, %1}, %2;" : "=f"(a), "=f"(b) : "l"(v));
}
__device__ __forceinline__ float sigm(float x) {
    return __fdividef(1.0f, 1.0f + __expf(-x));   // MUFU.EX2 + MUFU.RCP
}

// ---------------- k_build: per-graph CSR (count+scan+scatter fused) -------
// CSR entries stored as local byte offsets: (src - base_n) * 128
__global__ __launch_bounds__(1024) void k_build(const int* __restrict__ src,
                                                const int* __restrict__ dst) {
    __shared__ int s_cin[NPG];
    __shared__ int s_cout[NPG];
    __shared__ int s_scan[NPG];
    __shared__ int s_fill[NPG];
    int g = blockIdx.x, t = threadIdx.x;
    int base_n = g * NPG, base_e = g * EPG;

    s_cin[t] = 0; s_cout[t] = 0;
    __syncthreads();
#pragma unroll
    for (int it = 0; it < 16; it++) {
        int e = base_e + it * 1024 + t;
        atomicAdd(&s_cin[dst[e] - base_n], 1);
        atomicAdd(&s_cout[src[e] - base_n], 1);
    }
    __syncthreads();
    int v = s_cin[t];
    s_scan[t] = v;
    __syncthreads();
    for (int ofs = 1; ofs < 1024; ofs <<= 1) {
        int x = (t >= ofs) ? s_scan[t - ofs] : 0;
        __syncthreads();
        s_scan[t] += x;
        __syncthreads();
    }
    int excl = s_scan[t] - v;
    g_rowptr[base_n + t] = base_e + excl;
    g_rs_in[base_n + t]  = rsqrtf((float)max(v, 1));
    g_rs_out[base_n + t] = rsqrtf((float)max(s_cout[t], 1));
    s_fill[t] = excl;
    if (g == BB - 1 && t == 1023) g_rowptr[NN] = EE;
    __syncthreads();
#pragma unroll
    for (int it = 0; it < 16; it++) {
        int e = base_e + it * 1024 + t;
        int d = dst[e] - base_n;
        int pos = atomicAdd(&s_fill[d], 1);
        g_csr[base_e + pos] = (src[e] - base_n) * 128;   // byte offset, 32-float rows
    }
}

// ---------------- gather loop over pre-scaled byte offsets ----------------
__device__ __forceinline__ float gather_sum(const int* __restrict__ s_csr,
                                            const char* __restrict__ fb,
                                            int beg, int end) {
    float a = 0.f;
    int e = beg;
    while (e < end && (e & 3)) { a += *(const float*)(fb + s_csr[e]); e++; }
    for (; e + 3 < end; e += 4) {
        int4 o = *(const int4*)&s_csr[e];
        a += (*(const float*)(fb + o.x) + *(const float*)(fb + o.y)) +
             (*(const float*)(fb + o.z) + *(const float*)(fb + o.w));
    }
    for (; e < end; e++) a += *(const float*)(fb + s_csr[e]);
    return a;
}

// ---------------- smem-staged aggregation of input features ---------------
__global__ __launch_bounds__(1024) void k_agg1s(const float* __restrict__ feat) {
    extern __shared__ __align__(16) char s_raw[];
    float* s_f = (float*)s_raw;                    // 1024*32 floats
    int* s_csr = (int*)(s_raw + NPG * 32 * 4);     // 16384 ints (byte offsets)
    int g = blockIdx.x, h = blockIdx.y;
    int base_n = g * NPG, base_e = g * EPG;
    int t = threadIdx.x;

#pragma unroll
    for (int it = 0; it < 8; it++) {
        int idx = it * 1024 + t;                   // 8192 float4s
        int row = idx >> 3, q = idx & 7;
        float rs = g_rs_out[base_n + row];
        float4 v = *(const float4*)&feat[(size_t)(base_n + row) * INF + h * 32 + q * 4];
        v.x *= rs; v.y *= rs; v.z *= rs; v.w *= rs;
        *(float4*)&s_f[row * 32 + q * 4] = v;
    }
#pragma unroll
    for (int it = 0; it < 4; it++) {
        ((int4*)s_csr)[it * 1024 + t] = ((const int4*)(g_csr + base_e))[it * 1024 + t];
    }
    __syncthreads();

    int warp = t >> 5, lane = t & 31;
    const char* fb = (const char*)s_f + lane * 4;
#pragma unroll 1
    for (int i = 0; i < 32; i++) {
        int n = base_n + warp * 32 + i;
        int beg = g_rowptr[n] - base_e, end = g_rowptr[n + 1] - base_e;
        float a = gather_sum(s_csr, fb, beg, end);
        g_a[(size_t)n * INF + h * 32 + lane] = a * g_rs_in[n];
    }
}

// ---------------- smem-staged aggregation of p -> q -----------------------
__global__ __launch_bounds__(1024) void k_agg2s() {
    extern __shared__ __align__(16) char s_raw[];
    float* s_f = (float*)s_raw;
    int* s_csr = (int*)(s_raw + NPG * 32 * 4);
    int g = blockIdx.x, h = blockIdx.y;
    int base_n = g * NPG, base_e = g * EPG;
    int t = threadIdx.x;

#pragma unroll
    for (int it = 0; it < 8; it++) {
        int idx = it * 1024 + t;
        int row = idx >> 3, q = idx & 7;
        float4 v = *(const float4*)&g_p[(size_t)(base_n + row) * 64 + h * 32 + q * 4];
        *(float4*)&s_f[row * 32 + q * 4] = v;
    }
#pragma unroll
    for (int it = 0; it < 4; it++) {
        ((int4*)s_csr)[it * 1024 + t] = ((const int4*)(g_csr + base_e))[it * 1024 + t];
    }
    __syncthreads();

    int warp = t >> 5, lane = t & 31;
    const char* fb = (const char*)s_f + lane * 4;
#pragma unroll 1
    for (int i = 0; i < 32; i++) {
        int n = base_n + warp * 32 + i;
        int beg = g_rowptr[n] - base_e, end = g_rowptr[n + 1] - base_e;
        float a = gather_sum(s_csr, fb, beg, end);
        g_q[(size_t)n * 64 + h * 32 + lane] = a * g_rs_in[n];
    }
}

// ---------------- z epilogue: mean/ls/z from q ----------------------------
__global__ __launch_bounds__(256) void k_z(const float* __restrict__ noise,
                                           const float* __restrict__ b2,
                                           const float* __restrict__ b3,
                                           float* __restrict__ out_mean,
                                           float* __restrict__ out_ls) {
    int idx = blockIdx.x * 256 + threadIdx.x;     // 0 .. NN*32-1
    int n = idx >> 5, l = idx & 31;
    float mean = g_q[(size_t)n * 64 + l] + b2[l];
    float ls   = g_q[(size_t)n * 64 + 32 + l] + b3[l];
    float z    = fmaf(noise[idx], __expf(ls), mean);
    out_mean[idx] = mean;
    out_ls[idx]   = ls;
    g_z[idx]      = z;
}

// ---------------- fused MLP: h=relu(aW1+b1); p=(h*rs)@[W2|W3] -------------
__global__ __launch_bounds__(256, 2) void k_mlp(const float* __restrict__ W1,
                                                const float* __restrict__ b1,
                                                const float* __restrict__ W2,
                                                const float* __restrict__ W3) {
    extern __shared__ __align__(16) char s_raw[];
    float* sH   = (float*)s_raw;               // 128*132 : h^T scaled
    float* sA   = sH + 128 * 132;              // 32*132  : a^T chunk
    float* sW   = sA + 32 * 132;               // 32*128 stage1 / 32*64 stage2
    float* s_rs = sW + 32 * 128;               // 128
    float* s_b1 = s_rs + 128;                  // 128

    int tid = threadIdx.x;
    int n0 = blockIdx.x * 128;
    if (tid < 128) {
        s_rs[tid] = g_rs_out[n0 + tid];
        s_b1[tid] = b1[tid];
    }
    int tx = tid & 15, ty = tid >> 4;

    u64 acc[8][4];
#pragma unroll
    for (int r = 0; r < 8; r++)
#pragma unroll
        for (int cp = 0; cp < 4; cp++) acc[r][cp] = 0ull;

    for (int kc = 0; kc < 2; kc++) {
        __syncthreads();
#pragma unroll
        for (int it = 0; it < 4; it++) {
            int idx = it * 256 + tid;              // float4 idx, 1024 total
            int r = idx >> 3, k4 = (idx & 7) * 4;
            float4 v = *(const float4*)&g_a[(size_t)(n0 + r) * INF + kc * 32 + k4];
            sA[(k4 + 0) * 132 + r] = v.x;
            sA[(k4 + 1) * 132 + r] = v.y;
            sA[(k4 + 2) * 132 + r] = v.z;
            sA[(k4 + 3) * 132 + r] = v.w;
        }
#pragma unroll
        for (int it = 0; it < 4; it++) {
            int idx = it * 256 + tid;
            ((float4*)sW)[idx] = ((const float4*)(W1 + kc * 32 * 128))[idx];
        }
        __syncthreads();
#pragma unroll 4
        for (int k = 0; k < 32; k++) {
            const float* Ak = &sA[k * 132];
            const float* Wk = &sW[k * 128];
            float4 a0 = *(const float4*)&Ak[ty * 8];
            float4 a1 = *(const float4*)&Ak[ty * 8 + 4];
            float4 w0 = *(const float4*)&Wk[tx * 8];
            float4 w1 = *(const float4*)&Wk[tx * 8 + 4];
            u64 bp[4] = {pack2(w0.x, w0.y), pack2(w0.z, w0.w),
                         pack2(w1.x, w1.y), pack2(w1.z, w1.w)};
            float ar[8] = {a0.x, a0.y, a0.z, a0.w, a1.x, a1.y, a1.z, a1.w};
#pragma unroll
            for (int r = 0; r < 8; r++) {
                u64 ab = pack2(ar[r], ar[r]);
#pragma unroll
                for (int cp = 0; cp < 4; cp++) acc[r][cp] = fma2(ab, bp[cp], acc[r][cp]);
            }
        }
    }
    __syncthreads();

#pragma unroll
    for (int r = 0; r < 8; r++) {
        int row = ty * 8 + r;
        float rs = s_rs[row];
#pragma unroll
        for (int cp = 0; cp < 4; cp++) {
            float x, y;
            unpack2(acc[r][cp], x, y);
            int c0 = tx * 8 + 2 * cp;
            x = fmaxf(x + s_b1[c0], 0.f) * rs;
            y = fmaxf(y + s_b1[c0 + 1], 0.f) * rs;
            sH[(c0) * 132 + row]     = x;
            sH[(c0 + 1) * 132 + row] = y;
        }
    }

    u64 acc2[8][2];
#pragma unroll
    for (int r = 0; r < 8; r++) { acc2[r][0] = 0ull; acc2[r][1] = 0ull; }

    for (int kc = 0; kc < 4; kc++) {
        __syncthreads();
        {
            int idx = tid;                          // float4 idx, 512 total
#pragma unroll
            for (int it = 0; it < 2; it++, idx += 256) {
                int k = idx >> 4, c4 = (idx & 15) * 4;
                int kr = kc * 32 + k;
                float4 v;
                if (c4 < 32) v = *(const float4*)&W2[kr * 32 + c4];
                else         v = *(const float4*)&W3[kr * 32 + (c4 - 32)];
                *(float4*)&sW[k * 64 + c4] = v;
            }
        }
        __syncthreads();
#pragma unroll 4
        for (int k = 0; k < 32; k++) {
            const float* Ak = &sH[(kc * 32 + k) * 132];
            const float* Wk = &sW[k * 64];
            float4 a0 = *(const float4*)&Ak[ty * 8];
            float4 a1 = *(const float4*)&Ak[ty * 8 + 4];
            float4 w0 = *(const float4*)&Wk[tx * 4];
            u64 bp[2] = {pack2(w0.x, w0.y), pack2(w0.z, w0.w)};
            float ar[8] = {a0.x, a0.y, a0.z, a0.w, a1.x, a1.y, a1.z, a1.w};
#pragma unroll
            for (int r = 0; r < 8; r++) {
                u64 ab = pack2(ar[r], ar[r]);
                acc2[r][0] = fma2(ab, bp[0], acc2[r][0]);
                acc2[r][1] = fma2(ab, bp[1], acc2[r][1]);
            }
        }
    }
#pragma unroll
    for (int r = 0; r < 8; r++) {
        float v[4];
        unpack2(acc2[r][0], v[0], v[1]);
        unpack2(acc2[r][1], v[2], v[3]);
        *(float4*)&g_p[(size_t)(n0 + ty * 8 + r) * 64 + tx * 4] =
            make_float4(v[0], v[1], v[2], v[3]);
    }
}

// ---------------- adj = sigmoid(Z Z^T): upper-tri + mirror, zero-mov loop --
// sAdup[k][r] holds (a,a) duplicated u64; sB[k][132] plain floats, B pairs
// read directly as u64 (consecutive cols). Mainloop: 6 LDS.128 + 32 FFMA2 / k.
__global__ __launch_bounds__(256, 2) void k_adj(float* __restrict__ out) {
    extern __shared__ __align__(16) char s_raw[];
    u64*   sAd = (u64*)s_raw;                    // 32*128 u64 = 32 KB
    float* sB  = (float*)(s_raw + 32 * 128 * 8); // 32*132 floats

    int g = blockIdx.y;
    int t = blockIdx.x, bi = 0;
    while (t >= 8 - bi) { t -= 8 - bi; bi++; }
    int bj = bi + t;
    int i0 = bi * 128, j0 = bj * 128;

    const float4* zA4 = (const float4*)(g_z + ((size_t)(g * NPG + i0)) * OUTF);
    const float4* zB4 = (const float4*)(g_z + ((size_t)(g * NPG + j0)) * OUTF);
    int tid = threadIdx.x;

#pragma unroll
    for (int it = 0; it < 4; it++) {
        int idx = it * 256 + tid;                  // float4 idx, 1024 total
        int r = idx >> 3, k4 = (idx & 7) * 4;
        float4 va = zA4[idx];
        float4 vb = zB4[idx];
        sAd[(k4 + 0) * 128 + r] = pack2(va.x, va.x);
        sAd[(k4 + 1) * 128 + r] = pack2(va.y, va.y);
        sAd[(k4 + 2) * 128 + r] = pack2(va.z, va.z);
        sAd[(k4 + 3) * 128 + r] = pack2(va.w, va.w);
        sB[(k4 + 0) * 132 + r] = vb.x;
        sB[(k4 + 1) * 132 + r] = vb.y;
        sB[(k4 + 2) * 132 + r] = vb.z;
        sB[(k4 + 3) * 132 + r] = vb.w;
    }
    __syncthreads();

    int tx = tid & 15, ty = tid >> 4;
    u64 acc[8][4];
#pragma unroll
    for (int r = 0; r < 8; r++)
#pragma unroll
        for (int cp = 0; cp < 4; cp++) acc[r][cp] = 0ull;

#pragma unroll 4
    for (int k = 0; k < 32; k++) {
        const u64* Ad = &sAd[k * 128 + ty * 8];
        const float* Bk = &sB[k * 132 + tx * 8];
        ulonglong2 ap01 = *(const ulonglong2*)&Ad[0];
        ulonglong2 ap23 = *(const ulonglong2*)&Ad[2];
        ulonglong2 ap45 = *(const ulonglong2*)&Ad[4];
        ulonglong2 ap67 = *(const ulonglong2*)&Ad[6];
        ulonglong2 bp01 = *(const ulonglong2*)&Bk[0];
        ulonglong2 bp23 = *(const ulonglong2*)&Bk[4];
        u64 ap[8] = {ap01.x, ap01.y, ap23.x, ap23.y, ap45.x, ap45.y, ap67.x, ap67.y};
        u64 bp[4] = {bp01.x, bp01.y, bp23.x, bp23.y};
#pragma unroll
        for (int r = 0; r < 8; r++) {
#pragma unroll
            for (int cp = 0; cp < 4; cp++) acc[r][cp] = fma2(ap[r], bp[cp], acc[r][cp]);
        }
    }

    float m[8][8];
#pragma unroll
    for (int r = 0; r < 8; r++)
#pragma unroll
        for (int cp = 0; cp < 4; cp++) {
            float x, y;
            unpack2(acc[r][cp], x, y);
            m[r][2 * cp]     = sigm(x);
            m[r][2 * cp + 1] = sigm(y);
        }

    float* ob = out + ((size_t)(g * NPG + i0)) * NPG + j0;
#pragma unroll
    for (int r = 0; r < 8; r++) {
        float* o = &ob[(size_t)(ty * 8 + r) * NPG + tx * 8];
        *(float4*)&o[0] = make_float4(m[r][0], m[r][1], m[r][2], m[r][3]);
        *(float4*)&o[4] = make_float4(m[r][4], m[r][5], m[r][6], m[r][7]);
    }
    if (bi != bj) {
        float* obT = out + ((size_t)(g * NPG + j0)) * NPG + i0;
#pragma unroll
        for (int c = 0; c < 8; c++) {
            float* o = &obT[(size_t)(tx * 8 + c) * NPG + ty * 8];
            *(float4*)&o[0] = make_float4(m[0][c], m[1][c], m[2][c], m[3][c]);
            *(float4*)&o[4] = make_float4(m[4][c], m[5][c], m[6][c], m[7][c]);
        }
    }
}

// ---------------- launch ---------------------------------------------------
extern "C" void kernel_launch(void* const* d_in, const int* in_sizes, int n_in,
                              void* d_out, int out_size) {
    const float* features = (const float*)d_in[0];
    const int*   src      = (const int*)d_in[1];
    const int*   dst      = (const int*)d_in[2];
    const float* noise    = (const float*)d_in[3];
    const float* W1       = (const float*)d_in[4];
    const float* b1       = (const float*)d_in[5];
    const float* W2       = (const float*)d_in[6];
    const float* b2       = (const float*)d_in[7];
    const float* W3       = (const float*)d_in[8];
    const float* b3       = (const float*)d_in[9];

    float* out      = (float*)d_out;
    float* out_adj  = out;
    float* out_mean = out + MEAN_OFF;
    float* out_ls   = out + LS_OFF;

    static int smem_set = 0;
    if (!smem_set) {
        cudaFuncSetAttribute(k_agg1s, cudaFuncAttributeMaxDynamicSharedMemorySize, AGG_SMEM);
        cudaFuncSetAttribute(k_agg2s, cudaFuncAttributeMaxDynamicSharedMemorySize, AGG_SMEM);
        cudaFuncSetAttribute(k_mlp,   cudaFuncAttributeMaxDynamicSharedMemorySize, MLP_SMEM);
        cudaFuncSetAttribute(k_adj,   cudaFuncAttributeMaxDynamicSharedMemorySize, ADJ_SMEM);
        smem_set = 1;
    }

    k_build<<<BB, 1024>>>(src, dst);
    k_agg1s<<<dim3(BB, 2), 1024, AGG_SMEM>>>(features);
    k_mlp<<<512, 256, MLP_SMEM>>>(W1, b1, W2, W3);
    k_agg2s<<<dim3(BB, 2), 1024, AGG_SMEM>>>();
    k_z<<<NN * 32 / 256, 256>>>(noise, b2, b3, out_mean, out_ls);
    k_adj<<<dim3(36, BB), 256, ADJ_SMEM>>>(out_adj);
}

// round 10
// speedup vs baseline: 1.1323x; 1.1323x over previous
#include <cuda_runtime.h>
#include <math.h>

#define BB   64
#define NPG  1024
#define NN   (BB * NPG)       // 65536 nodes
#define EE   (BB * 16384)     // 1048576 edges
#define EPG  16384            // edges per graph
#define INF  64
#define HIDF 128
#define OUTF 32

#define ADJ_ELEMS  ((size_t)BB * NPG * NPG)   // 67108864
#define MEAN_OFF   ADJ_ELEMS
#define LS_OFF     (ADJ_ELEMS + (size_t)NN * OUTF)

#define AGG_SMEM   (NPG * 32 * 4 + EPG * 4)   // 196608 B
// k_mlp dynamic smem: sH(128*132) + sA(32*132) + sW(32*128) + rs(128) + b1(128)
#define MLP_SMEM   ((128 * 132 + 32 * 132 + 32 * 128 + 256) * 4)   // 101888 B

// ---------------- scratch (static device globals; no runtime alloc) -------
__device__ float g_rs_out[NN];
__device__ float g_rs_in[NN];
__device__ int   g_rowptr[NN + 1];
__device__ int   g_csr[EE];        // pre-scaled LOCAL byte offsets (src*128)
__device__ float g_a[NN * INF];    // aggregated+scaled input features
__device__ float g_p[NN * 64];     // (h * rs_out) @ [W2 | W3]
__device__ float g_q[NN * 64];     // aggregated p (pre-bias mean|log_std)
__device__ float g_z[NN * OUTF];   // latent z

typedef unsigned long long u64;

// ---------------- f32x2 helpers (FFMA2) -----------------------------------
__device__ __forceinline__ u64 pack2(float lo, float hi) {
    u64 r;
    asm("mov.b64 %0, {%1, %2};" : "=l"(r) : "f"(lo), "f"(hi));
    return r;
}
__device__ __forceinline__ u64 fma2(u64 a, u64 b, u64 c) {
    u64 d;
    asm("fma.rn.f32x2 %0, %1, %2, %3;" : "=l"(d) : "l"(a), "l"(b), "l"(c));
    return d;
}
__device__ __forceinline__ void unpack2(u64 v, float& a, float& b) {
    asm("mov.b64 {%0, %1}, %2;" : "=f"(a), "=f"(b) : "l"(v));
}
__device__ __forceinline__ float sigm(float x) {
    return __fdividef(1.0f, 1.0f + __expf(-x));   // MUFU.EX2 + MUFU.RCP
}

// ---------------- k_build: per-graph CSR (count+scan+scatter fused) -------
// CSR entries stored as local byte offsets: (src - base_n) * 128
__global__ __launch_bounds__(1024) void k_build(const int* __restrict__ src,
                                                const int* __restrict__ dst) {
    __shared__ int s_cin[NPG];
    __shared__ int s_cout[NPG];
    __shared__ int s_scan[NPG];
    __shared__ int s_fill[NPG];
    int g = blockIdx.x, t = threadIdx.x;
    int base_n = g * NPG, base_e = g * EPG;

    s_cin[t] = 0; s_cout[t] = 0;
    __syncthreads();
#pragma unroll
    for (int it = 0; it < 16; it++) {
        int e = base_e + it * 1024 + t;
        atomicAdd(&s_cin[dst[e] - base_n], 1);
        atomicAdd(&s_cout[src[e] - base_n], 1);
    }
    __syncthreads();
    int v = s_cin[t];
    s_scan[t] = v;
    __syncthreads();
    for (int ofs = 1; ofs < 1024; ofs <<= 1) {
        int x = (t >= ofs) ? s_scan[t - ofs] : 0;
        __syncthreads();
        s_scan[t] += x;
        __syncthreads();
    }
    int excl = s_scan[t] - v;
    g_rowptr[base_n + t] = base_e + excl;
    g_rs_in[base_n + t]  = rsqrtf((float)max(v, 1));
    g_rs_out[base_n + t] = rsqrtf((float)max(s_cout[t], 1));
    s_fill[t] = excl;
    if (g == BB - 1 && t == 1023) g_rowptr[NN] = EE;
    __syncthreads();
#pragma unroll
    for (int it = 0; it < 16; it++) {
        int e = base_e + it * 1024 + t;
        int d = dst[e] - base_n;
        int pos = atomicAdd(&s_fill[d], 1);
        g_csr[base_e + pos] = (src[e] - base_n) * 128;   // byte offset, 32-float rows
    }
}

// ---------------- gather loop over pre-scaled byte offsets ----------------
__device__ __forceinline__ float gather_sum(const int* __restrict__ s_csr,
                                            const char* __restrict__ fb,
                                            int beg, int end) {
    float a = 0.f;
    int e = beg;
    while (e < end && (e & 3)) { a += *(const float*)(fb + s_csr[e]); e++; }
    for (; e + 3 < end; e += 4) {
        int4 o = *(const int4*)&s_csr[e];
        a += (*(const float*)(fb + o.x) + *(const float*)(fb + o.y)) +
             (*(const float*)(fb + o.z) + *(const float*)(fb + o.w));
    }
    for (; e < end; e++) a += *(const float*)(fb + s_csr[e]);
    return a;
}

// ---------------- smem-staged aggregation of input features ---------------
// rowptr / rs_in cached in registers per warp, shfl'd per node
__global__ __launch_bounds__(1024) void k_agg1s(const float* __restrict__ feat) {
    extern __shared__ __align__(16) char s_raw[];
    float* s_f = (float*)s_raw;                    // 1024*32 floats
    int* s_csr = (int*)(s_raw + NPG * 32 * 4);     // 16384 ints (byte offsets)
    int g = blockIdx.x, h = blockIdx.y;
    int base_n = g * NPG, base_e = g * EPG;
    int t = threadIdx.x;

#pragma unroll
    for (int it = 0; it < 8; it++) {
        int idx = it * 1024 + t;                   // 8192 float4s
        int row = idx >> 3, q = idx & 7;
        float rs = g_rs_out[base_n + row];
        float4 v = *(const float4*)&feat[(size_t)(base_n + row) * INF + h * 32 + q * 4];
        v.x *= rs; v.y *= rs; v.z *= rs; v.w *= rs;
        *(float4*)&s_f[row * 32 + q * 4] = v;
    }
#pragma unroll
    for (int it = 0; it < 4; it++) {
        ((int4*)s_csr)[it * 1024 + t] = ((const int4*)(g_csr + base_e))[it * 1024 + t];
    }

    int warp = t >> 5, lane = t & 31;
    int node_l = base_n + warp * 32 + lane;
    int rpA = g_rowptr[node_l] - base_e;
    int rpB = g_rowptr[node_l + 1] - base_e;
    float rinv = g_rs_in[node_l];
    __syncthreads();

    const char* fb = (const char*)s_f + lane * 4;
    float* outp = &g_a[(size_t)(base_n + warp * 32) * INF + h * 32 + lane];
#pragma unroll 1
    for (int i = 0; i < 32; i++) {
        int beg = __shfl_sync(0xffffffffu, rpA, i);
        int end = __shfl_sync(0xffffffffu, rpB, i);
        float rin = __shfl_sync(0xffffffffu, rinv, i);
        float a = gather_sum(s_csr, fb, beg, end);
        outp[(size_t)i * INF] = a * rin;
    }
}

// ---------------- smem-staged aggregation of p -> q -----------------------
__global__ __launch_bounds__(1024) void k_agg2s() {
    extern __shared__ __align__(16) char s_raw[];
    float* s_f = (float*)s_raw;
    int* s_csr = (int*)(s_raw + NPG * 32 * 4);
    int g = blockIdx.x, h = blockIdx.y;
    int base_n = g * NPG, base_e = g * EPG;
    int t = threadIdx.x;

#pragma unroll
    for (int it = 0; it < 8; it++) {
        int idx = it * 1024 + t;
        int row = idx >> 3, q = idx & 7;
        float4 v = *(const float4*)&g_p[(size_t)(base_n + row) * 64 + h * 32 + q * 4];
        *(float4*)&s_f[row * 32 + q * 4] = v;
    }
#pragma unroll
    for (int it = 0; it < 4; it++) {
        ((int4*)s_csr)[it * 1024 + t] = ((const int4*)(g_csr + base_e))[it * 1024 + t];
    }

    int warp = t >> 5, lane = t & 31;
    int node_l = base_n + warp * 32 + lane;
    int rpA = g_rowptr[node_l] - base_e;
    int rpB = g_rowptr[node_l + 1] - base_e;
    float rinv = g_rs_in[node_l];
    __syncthreads();

    const char* fb = (const char*)s_f + lane * 4;
    float* outp = &g_q[(size_t)(base_n + warp * 32) * 64 + h * 32 + lane];
#pragma unroll 1
    for (int i = 0; i < 32; i++) {
        int beg = __shfl_sync(0xffffffffu, rpA, i);
        int end = __shfl_sync(0xffffffffu, rpB, i);
        float rin = __shfl_sync(0xffffffffu, rinv, i);
        float a = gather_sum(s_csr, fb, beg, end);
        outp[(size_t)i * 64] = a * rin;
    }
}

// ---------------- z epilogue: mean/ls/z from q ----------------------------
__global__ __launch_bounds__(256) void k_z(const float* __restrict__ noise,
                                           const float* __restrict__ b2,
                                           const float* __restrict__ b3,
                                           float* __restrict__ out_mean,
                                           float* __restrict__ out_ls) {
    int idx = blockIdx.x * 256 + threadIdx.x;     // 0 .. NN*32-1
    int n = idx >> 5, l = idx & 31;
    float mean = g_q[(size_t)n * 64 + l] + b2[l];
    float ls   = g_q[(size_t)n * 64 + 32 + l] + b3[l];
    float z    = fmaf(noise[idx], __expf(ls), mean);
    out_mean[idx] = mean;
    out_ls[idx]   = ls;
    g_z[idx]      = z;
}

// ---------------- fused MLP: h=relu(aW1+b1); p=(h*rs)@[W2|W3] -------------
__global__ __launch_bounds__(256, 2) void k_mlp(const float* __restrict__ W1,
                                                const float* __restrict__ b1,
                                                const float* __restrict__ W2,
                                                const float* __restrict__ W3) {
    extern __shared__ __align__(16) char s_raw[];
    float* sH   = (float*)s_raw;               // 128*132 : h^T scaled
    float* sA   = sH + 128 * 132;              // 32*132  : a^T chunk
    float* sW   = sA + 32 * 132;               // 32*128 stage1 / 32*64 stage2
    float* s_rs = sW + 32 * 128;               // 128
    float* s_b1 = s_rs + 128;                  // 128

    int tid = threadIdx.x;
    int n0 = blockIdx.x * 128;
    if (tid < 128) {
        s_rs[tid] = g_rs_out[n0 + tid];
        s_b1[tid] = b1[tid];
    }
    int tx = tid & 15, ty = tid >> 4;

    u64 acc[8][4];
#pragma unroll
    for (int r = 0; r < 8; r++)
#pragma unroll
        for (int cp = 0; cp < 4; cp++) acc[r][cp] = 0ull;

    for (int kc = 0; kc < 2; kc++) {
        __syncthreads();
#pragma unroll
        for (int it = 0; it < 4; it++) {
            int idx = it * 256 + tid;              // float4 idx, 1024 total
            int r = idx >> 3, k4 = (idx & 7) * 4;
            float4 v = *(const float4*)&g_a[(size_t)(n0 + r) * INF + kc * 32 + k4];
            sA[(k4 + 0) * 132 + r] = v.x;
            sA[(k4 + 1) * 132 + r] = v.y;
            sA[(k4 + 2) * 132 + r] = v.z;
            sA[(k4 + 3) * 132 + r] = v.w;
        }
#pragma unroll
        for (int it = 0; it < 4; it++) {
            int idx = it * 256 + tid;
            ((float4*)sW)[idx] = ((const float4*)(W1 + kc * 32 * 128))[idx];
        }
        __syncthreads();
#pragma unroll 4
        for (int k = 0; k < 32; k++) {
            const float* Ak = &sA[k * 132];
            const float* Wk = &sW[k * 128];
            float4 a0 = *(const float4*)&Ak[ty * 8];
            float4 a1 = *(const float4*)&Ak[ty * 8 + 4];
            float4 w0 = *(const float4*)&Wk[tx * 8];
            float4 w1 = *(const float4*)&Wk[tx * 8 + 4];
            u64 bp[4] = {pack2(w0.x, w0.y), pack2(w0.z, w0.w),
                         pack2(w1.x, w1.y), pack2(w1.z, w1.w)};
            float ar[8] = {a0.x, a0.y, a0.z, a0.w, a1.x, a1.y, a1.z, a1.w};
#pragma unroll
            for (int r = 0; r < 8; r++) {
                u64 ab = pack2(ar[r], ar[r]);
#pragma unroll
                for (int cp = 0; cp < 4; cp++) acc[r][cp] = fma2(ab, bp[cp], acc[r][cp]);
            }
        }
    }
    __syncthreads();

#pragma unroll
    for (int r = 0; r < 8; r++) {
        int row = ty * 8 + r;
        float rs = s_rs[row];
#pragma unroll
        for (int cp = 0; cp < 4; cp++) {
            float x, y;
            unpack2(acc[r][cp], x, y);
            int c0 = tx * 8 + 2 * cp;
            x = fmaxf(x + s_b1[c0], 0.f) * rs;
            y = fmaxf(y + s_b1[c0 + 1], 0.f) * rs;
            sH[(c0) * 132 + row]     = x;
            sH[(c0 + 1) * 132 + row] = y;
        }
    }

    u64 acc2[8][2];
#pragma unroll
    for (int r = 0; r < 8; r++) { acc2[r][0] = 0ull; acc2[r][1] = 0ull; }

    for (int kc = 0; kc < 4; kc++) {
        __syncthreads();
        {
            int idx = tid;                          // float4 idx, 512 total
#pragma unroll
            for (int it = 0; it < 2; it++, idx += 256) {
                int k = idx >> 4, c4 = (idx & 15) * 4;
                int kr = kc * 32 + k;
                float4 v;
                if (c4 < 32) v = *(const float4*)&W2[kr * 32 + c4];
                else         v = *(const float4*)&W3[kr * 32 + (c4 - 32)];
                *(float4*)&sW[k * 64 + c4] = v;
            }
        }
        __syncthreads();
#pragma unroll 4
        for (int k = 0; k < 32; k++) {
            const float* Ak = &sH[(kc * 32 + k) * 132];
            const float* Wk = &sW[k * 64];
            float4 a0 = *(const float4*)&Ak[ty * 8];
            float4 a1 = *(const float4*)&Ak[ty * 8 + 4];
            float4 w0 = *(const float4*)&Wk[tx * 4];
            u64 bp[2] = {pack2(w0.x, w0.y), pack2(w0.z, w0.w)};
            float ar[8] = {a0.x, a0.y, a0.z, a0.w, a1.x, a1.y, a1.z, a1.w};
#pragma unroll
            for (int r = 0; r < 8; r++) {
                u64 ab = pack2(ar[r], ar[r]);
                acc2[r][0] = fma2(ab, bp[0], acc2[r][0]);
                acc2[r][1] = fma2(ab, bp[1], acc2[r][1]);
            }
        }
    }
#pragma unroll
    for (int r = 0; r < 8; r++) {
        float v[4];
        unpack2(acc2[r][0], v[0], v[1]);
        unpack2(acc2[r][1], v[2], v[3]);
        *(float4*)&g_p[(size_t)(n0 + ty * 8 + r) * 64 + tx * 4] =
            make_float4(v[0], v[1], v[2], v[3]);
    }
}

// ---------------- adj = sigmoid(Z Z^T): upper-tri + mirror -----------------
// Conflict-free [k][132] float tiles; ROW-PAIR accumulators: A pairs come
// directly from LDS.128 (zero packing movs), B duplicated via 8 movs.
__global__ __launch_bounds__(256, 2) void k_adj(float* __restrict__ out) {
    __shared__ __align__(16) float sA[32 * 132];
    __shared__ __align__(16) float sB[32 * 132];

    int g = blockIdx.y;
    int t = blockIdx.x, bi = 0;
    while (t >= 8 - bi) { t -= 8 - bi; bi++; }
    int bj = bi + t;
    int i0 = bi * 128, j0 = bj * 128;

    const float4* zA4 = (const float4*)(g_z + ((size_t)(g * NPG + i0)) * OUTF);
    const float4* zB4 = (const float4*)(g_z + ((size_t)(g * NPG + j0)) * OUTF);
    int tid = threadIdx.x;

#pragma unroll
    for (int it = 0; it < 4; it++) {
        int idx = it * 256 + tid;                  // float4 idx, 1024 total
        int r = idx >> 3, k4 = (idx & 7) * 4;
        float4 va = zA4[idx];
        float4 vb = zB4[idx];
        sA[(k4 + 0) * 132 + r] = va.x;
        sA[(k4 + 1) * 132 + r] = va.y;
        sA[(k4 + 2) * 132 + r] = va.z;
        sA[(k4 + 3) * 132 + r] = va.w;
        sB[(k4 + 0) * 132 + r] = vb.x;
        sB[(k4 + 1) * 132 + r] = vb.y;
        sB[(k4 + 2) * 132 + r] = vb.z;
        sB[(k4 + 3) * 132 + r] = vb.w;
    }
    __syncthreads();

    int tx = tid & 15, ty = tid >> 4;
    // acc[rp][c]: row pair (ty*8+2rp, ty*8+2rp+1) x col (tx*8+c)
    u64 acc[4][8];
#pragma unroll
    for (int rp = 0; rp < 4; rp++)
#pragma unroll
        for (int c = 0; c < 8; c++) acc[rp][c] = 0ull;

#pragma unroll 4
    for (int k = 0; k < 32; k++) {
        const ulonglong2* Ap = (const ulonglong2*)&sA[k * 132 + ty * 8];
        ulonglong2 a01 = Ap[0], a23 = Ap[1];     // (r0,r1)(r2,r3)(r4,r5)(r6,r7)
        u64 ap[4] = {a01.x, a01.y, a23.x, a23.y};
        const float4* Bp = (const float4*)&sB[k * 132 + tx * 8];
        float4 b0 = Bp[0], b1 = Bp[1];
        u64 bp[8] = {pack2(b0.x, b0.x), pack2(b0.y, b0.y),
                     pack2(b0.z, b0.z), pack2(b0.w, b0.w),
                     pack2(b1.x, b1.x), pack2(b1.y, b1.y),
                     pack2(b1.z, b1.z), pack2(b1.w, b1.w)};
#pragma unroll
        for (int rp = 0; rp < 4; rp++)
#pragma unroll
            for (int c = 0; c < 8; c++) acc[rp][c] = fma2(ap[rp], bp[c], acc[rp][c]);
    }

    float m[8][8];     // m[r][c]
#pragma unroll
    for (int rp = 0; rp < 4; rp++)
#pragma unroll
        for (int c = 0; c < 8; c++) {
            float x, y;
            unpack2(acc[rp][c], x, y);
            m[2 * rp][c]     = sigm(x);
            m[2 * rp + 1][c] = sigm(y);
        }

    float* ob = out + ((size_t)(g * NPG + i0)) * NPG + j0;
#pragma unroll
    for (int r = 0; r < 8; r++) {
        float* o = &ob[(size_t)(ty * 8 + r) * NPG + tx * 8];
        *(float4*)&o[0] = make_float4(m[r][0], m[r][1], m[r][2], m[r][3]);
        *(float4*)&o[4] = make_float4(m[r][4], m[r][5], m[r][6], m[r][7]);
    }
    if (bi != bj) {
        float* obT = out + ((size_t)(g * NPG + j0)) * NPG + i0;
#pragma unroll
        for (int c = 0; c < 8; c++) {
            float* o = &obT[(size_t)(tx * 8 + c) * NPG + ty * 8];
            *(float4*)&o[0] = make_float4(m[0][c], m[1][c], m[2][c], m[3][c]);
            *(float4*)&o[4] = make_float4(m[4][c], m[5][c], m[6][c], m[7][c]);
        }
    }
}

// ---------------- launch ---------------------------------------------------
extern "C" void kernel_launch(void* const* d_in, const int* in_sizes, int n_in,
                              void* d_out, int out_size) {
    const float* features = (const float*)d_in[0];
    const int*   src      = (const int*)d_in[1];
    const int*   dst      = (const int*)d_in[2];
    const float* noise    = (const float*)d_in[3];
    const float* W1       = (const float*)d_in[4];
    const float* b1       = (const float*)d_in[5];
    const float* W2       = (const float*)d_in[6];
    const float* b2       = (const float*)d_in[7];
    const float* W3       = (const float*)d_in[8];
    const float* b3       = (const float*)d_in[9];

    float* out      = (float*)d_out;
    float* out_adj  = out;
    float* out_mean = out + MEAN_OFF;
    float* out_ls   = out + LS_OFF;

    static int smem_set = 0;
    if (!smem_set) {
        cudaFuncSetAttribute(k_agg1s, cudaFuncAttributeMaxDynamicSharedMemorySize, AGG_SMEM);
        cudaFuncSetAttribute(k_agg2s, cudaFuncAttributeMaxDynamicSharedMemorySize, AGG_SMEM);
        cudaFuncSetAttribute(k_mlp,   cudaFuncAttributeMaxDynamicSharedMemorySize, MLP_SMEM);
        smem_set = 1;
    }

    k_build<<<BB, 1024>>>(src, dst);
    k_agg1s<<<dim3(BB, 2), 1024, AGG_SMEM>>>(features);
    k_mlp<<<512, 256, MLP_SMEM>>>(W1, b1, W2, W3);
    k_agg2s<<<dim3(BB, 2), 1024, AGG_SMEM>>>();
    k_z<<<NN * 32 / 256, 256>>>(noise, b2, b3, out_mean, out_ls);
    k_adj<<<dim3(36, BB), 256>>>(out_adj);
}

// round 11
// speedup vs baseline: 1.1445x; 1.0108x over previous
#include <cuda_runtime.h>
#include <math.h>

#define BB   64
#define NPG  1024
#define NN   (BB * NPG)       // 65536 nodes
#define EE   (BB * 16384)     // 1048576 edges
#define EPG  16384            // edges per graph
#define EPG2 20480            // padded csr stride per graph (<= EPG + 4*NPG)
#define INF  64
#define HIDF 128
#define OUTF 32

#define DUMMY_OFF (1024 * 128)   // byte offset of the zero row in s_f

#define ADJ_ELEMS  ((size_t)BB * NPG * NPG)   // 67108864
#define MEAN_OFF   ADJ_ELEMS
#define LS_OFF     (ADJ_ELEMS + (size_t)NN * OUTF)

// s_f: 1025 rows x 32 floats (row 1024 = zeros); s_csr: EPG2 ints
#define AGG_SMEM   (1025 * 32 * 4 + EPG2 * 4)   // 131200 + 81920 = 213120 B
// k_mlp dynamic smem: sH(128*132) + sA(32*132) + sW(32*128) + rs(128) + b1(128)
#define MLP_SMEM   ((128 * 132 + 32 * 132 + 32 * 128 + 256) * 4)   // 101888 B

// ---------------- scratch (static device globals; no runtime alloc) -------
__device__ float g_rs_out[NN];
__device__ float g_rs_in[NN];
__device__ int   g_rp2[BB * (NPG + 1)];   // per-graph padded rowptr (local)
__device__ int   g_csr[BB * EPG2];        // pre-scaled LOCAL byte offsets
__device__ float g_a[NN * INF];    // aggregated+scaled input features
__device__ float g_p[NN * 64];     // (h * rs_out) @ [W2 | W3]
__device__ float g_q[NN * 64];     // aggregated p (pre-bias mean|log_std)
__device__ float g_z[NN * OUTF];   // latent z

typedef unsigned long long u64;

// ---------------- f32x2 helpers (FFMA2) -----------------------------------
__device__ __forceinline__ u64 pack2(float lo, float hi) {
    u64 r;
    asm("mov.b64 %0, {%1, %2};" : "=l"(r) : "f"(lo), "f"(hi));
    return r;
}
__device__ __forceinline__ u64 fma2(u64 a, u64 b, u64 c) {
    u64 d;
    asm("fma.rn.f32x2 %0, %1, %2, %3;" : "=l"(d) : "l"(a), "l"(b), "l"(c));
    return d;
}
__device__ __forceinline__ void unpack2(u64 v, float& a, float& b) {
    asm("mov.b64 {%0, %1}, %2;" : "=f"(a), "=f"(b) : "l"(v));
}
// sigmoid via single-MUFU tanh: sigma(x) = 0.5*tanh(0.5x) + 0.5
__device__ __forceinline__ float sigm(float x) {
    float t;
    float h = 0.5f * x;
    asm("tanh.approx.f32 %0, %1;" : "=f"(t) : "f"(h));
    return fmaf(0.5f, t, 0.5f);
}

// ---------------- k_build: per-graph padded CSR ----------------------------
// node segments padded to multiple of 4; pad entries -> DUMMY_OFF (zero row)
__global__ __launch_bounds__(1024) void k_build(const int* __restrict__ src,
                                                const int* __restrict__ dst) {
    __shared__ int s_cin[NPG];
    __shared__ int s_cout[NPG];
    __shared__ int s_scan[NPG];
    __shared__ int s_fill[NPG];
    int g = blockIdx.x, t = threadIdx.x;
    int base_n = g * NPG, base_e = g * EPG;
    int base_e2 = g * EPG2;

    s_cin[t] = 0; s_cout[t] = 0;
    __syncthreads();
#pragma unroll
    for (int it = 0; it < 16; it++) {
        int e = base_e + it * 1024 + t;
        atomicAdd(&s_cin[dst[e] - base_n], 1);
        atomicAdd(&s_cout[src[e] - base_n], 1);
    }
    __syncthreads();
    int v  = s_cin[t];
    int vp = (v + 3) & ~3;                 // padded count
    s_scan[t] = vp;
    __syncthreads();
    for (int ofs = 1; ofs < 1024; ofs <<= 1) {
        int x = (t >= ofs) ? s_scan[t - ofs] : 0;
        __syncthreads();
        s_scan[t] += x;
        __syncthreads();
    }
    int excl = s_scan[t] - vp;             // padded exclusive scan (local)
    g_rp2[g * (NPG + 1) + t] = excl;
    if (t == 1023) g_rp2[g * (NPG + 1) + 1024] = excl + vp;
    g_rs_in[base_n + t]  = rsqrtf((float)max(v, 1));
    g_rs_out[base_n + t] = rsqrtf((float)max(s_cout[t], 1));
    s_fill[t] = excl;
    __syncthreads();
#pragma unroll
    for (int it = 0; it < 16; it++) {
        int e = base_e + it * 1024 + t;
        int d = dst[e] - base_n;
        int pos = atomicAdd(&s_fill[d], 1);
        g_csr[base_e2 + pos] = (src[e] - base_n) * 128;   // byte offset
    }
    // fill this node's padding slots with the dummy zero-row offset
    for (int j = excl + v; j < excl + vp; j++)
        g_csr[base_e2 + j] = DUMMY_OFF;
}

// ---------------- branch-free gather over padded int4 groups --------------
__device__ __forceinline__ float gather_sum(const int* __restrict__ s_csr,
                                            const char* __restrict__ fb,
                                            int beg, int end) {
    float a = 0.f;
#pragma unroll 2
    for (int e = beg; e < end; e += 4) {
        int4 o = *(const int4*)&s_csr[e];
        a += (*(const float*)(fb + o.x) + *(const float*)(fb + o.y)) +
             (*(const float*)(fb + o.z) + *(const float*)(fb + o.w));
    }
    return a;
}

// ---------------- smem-staged aggregation of input features ---------------
__global__ __launch_bounds__(1024) void k_agg1s(const float* __restrict__ feat) {
    extern __shared__ __align__(16) char s_raw[];
    float* s_f = (float*)s_raw;                    // 1025*32 floats
    int* s_csr = (int*)(s_raw + 1025 * 32 * 4);    // EPG2 ints
    int g = blockIdx.x, h = blockIdx.y;
    int base_n = g * NPG;
    int t = threadIdx.x;

#pragma unroll
    for (int it = 0; it < 8; it++) {
        int idx = it * 1024 + t;                   // 8192 float4s
        int row = idx >> 3, q = idx & 7;
        float rs = g_rs_out[base_n + row];
        float4 v = *(const float4*)&feat[(size_t)(base_n + row) * INF + h * 32 + q * 4];
        v.x *= rs; v.y *= rs; v.z *= rs; v.w *= rs;
        *(float4*)&s_f[row * 32 + q * 4] = v;
    }
    if (t < 8) *(float4*)&s_f[1024 * 32 + t * 4] = make_float4(0.f, 0.f, 0.f, 0.f);
#pragma unroll
    for (int it = 0; it < 5; it++) {
        ((int4*)s_csr)[it * 1024 + t] = ((const int4*)(g_csr + g * EPG2))[it * 1024 + t];
    }

    int warp = t >> 5, lane = t & 31;
    const int* rp = &g_rp2[g * (NPG + 1) + warp * 32];
    int rpA = rp[lane];
    int rpB = rp[lane + 1];
    float rinv = g_rs_in[base_n + warp * 32 + lane];
    __syncthreads();

    const char* fb = (const char*)s_f + lane * 4;
    float* outp = &g_a[(size_t)(base_n + warp * 32) * INF + h * 32 + lane];
#pragma unroll 1
    for (int i = 0; i < 32; i++) {
        int beg = __shfl_sync(0xffffffffu, rpA, i);
        int end = __shfl_sync(0xffffffffu, rpB, i);
        float rin = __shfl_sync(0xffffffffu, rinv, i);
        float a = gather_sum(s_csr, fb, beg, end);
        outp[(size_t)i * INF] = a * rin;
    }
}

// ---------------- smem-staged aggregation of p -> q -----------------------
__global__ __launch_bounds__(1024) void k_agg2s() {
    extern __shared__ __align__(16) char s_raw[];
    float* s_f = (float*)s_raw;
    int* s_csr = (int*)(s_raw + 1025 * 32 * 4);
    int g = blockIdx.x, h = blockIdx.y;
    int base_n = g * NPG;
    int t = threadIdx.x;

#pragma unroll
    for (int it = 0; it < 8; it++) {
        int idx = it * 1024 + t;
        int row = idx >> 3, q = idx & 7;
        float4 v = *(const float4*)&g_p[(size_t)(base_n + row) * 64 + h * 32 + q * 4];
        *(float4*)&s_f[row * 32 + q * 4] = v;
    }
    if (t < 8) *(float4*)&s_f[1024 * 32 + t * 4] = make_float4(0.f, 0.f, 0.f, 0.f);
#pragma unroll
    for (int it = 0; it < 5; it++) {
        ((int4*)s_csr)[it * 1024 + t] = ((const int4*)(g_csr + g * EPG2))[it * 1024 + t];
    }

    int warp = t >> 5, lane = t & 31;
    const int* rp = &g_rp2[g * (NPG + 1) + warp * 32];
    int rpA = rp[lane];
    int rpB = rp[lane + 1];
    float rinv = g_rs_in[base_n + warp * 32 + lane];
    __syncthreads();

    const char* fb = (const char*)s_f + lane * 4;
    float* outp = &g_q[(size_t)(base_n + warp * 32) * 64 + h * 32 + lane];
#pragma unroll 1
    for (int i = 0; i < 32; i++) {
        int beg = __shfl_sync(0xffffffffu, rpA, i);
        int end = __shfl_sync(0xffffffffu, rpB, i);
        float rin = __shfl_sync(0xffffffffu, rinv, i);
        float a = gather_sum(s_csr, fb, beg, end);
        outp[(size_t)i * 64] = a * rin;
    }
}

// ---------------- z epilogue: mean/ls/z from q ----------------------------
__global__ __launch_bounds__(256) void k_z(const float* __restrict__ noise,
                                           const float* __restrict__ b2,
                                           const float* __restrict__ b3,
                                           float* __restrict__ out_mean,
                                           float* __restrict__ out_ls) {
    int idx = blockIdx.x * 256 + threadIdx.x;     // 0 .. NN*32-1
    int n = idx >> 5, l = idx & 31;
    float mean = g_q[(size_t)n * 64 + l] + b2[l];
    float ls   = g_q[(size_t)n * 64 + 32 + l] + b3[l];
    float z    = fmaf(noise[idx], __expf(ls), mean);
    out_mean[idx] = mean;
    out_ls[idx]   = ls;
    g_z[idx]      = z;
}

// ---------------- fused MLP: h=relu(aW1+b1); p=(h*rs)@[W2|W3] -------------
__global__ __launch_bounds__(256, 2) void k_mlp(const float* __restrict__ W1,
                                                const float* __restrict__ b1,
                                                const float* __restrict__ W2,
                                                const float* __restrict__ W3) {
    extern __shared__ __align__(16) char s_raw[];
    float* sH   = (float*)s_raw;               // 128*132 : h^T scaled
    float* sA   = sH + 128 * 132;              // 32*132  : a^T chunk
    float* sW   = sA + 32 * 132;               // 32*128 stage1 / 32*64 stage2
    float* s_rs = sW + 32 * 128;               // 128
    float* s_b1 = s_rs + 128;                  // 128

    int tid = threadIdx.x;
    int n0 = blockIdx.x * 128;
    if (tid < 128) {
        s_rs[tid] = g_rs_out[n0 + tid];
        s_b1[tid] = b1[tid];
    }
    int tx = tid & 15, ty = tid >> 4;

    u64 acc[8][4];
#pragma unroll
    for (int r = 0; r < 8; r++)
#pragma unroll
        for (int cp = 0; cp < 4; cp++) acc[r][cp] = 0ull;

    for (int kc = 0; kc < 2; kc++) {
        __syncthreads();
#pragma unroll
        for (int it = 0; it < 4; it++) {
            int idx = it * 256 + tid;              // float4 idx, 1024 total
            int r = idx >> 3, k4 = (idx & 7) * 4;
            float4 v = *(const float4*)&g_a[(size_t)(n0 + r) * INF + kc * 32 + k4];
            sA[(k4 + 0) * 132 + r] = v.x;
            sA[(k4 + 1) * 132 + r] = v.y;
            sA[(k4 + 2) * 132 + r] = v.z;
            sA[(k4 + 3) * 132 + r] = v.w;
        }
#pragma unroll
        for (int it = 0; it < 4; it++) {
            int idx = it * 256 + tid;
            ((float4*)sW)[idx] = ((const float4*)(W1 + kc * 32 * 128))[idx];
        }
        __syncthreads();
#pragma unroll 4
        for (int k = 0; k < 32; k++) {
            const float* Ak = &sA[k * 132];
            const float* Wk = &sW[k * 128];
            float4 a0 = *(const float4*)&Ak[ty * 8];
            float4 a1 = *(const float4*)&Ak[ty * 8 + 4];
            float4 w0 = *(const float4*)&Wk[tx * 8];
            float4 w1 = *(const float4*)&Wk[tx * 8 + 4];
            u64 bp[4] = {pack2(w0.x, w0.y), pack2(w0.z, w0.w),
                         pack2(w1.x, w1.y), pack2(w1.z, w1.w)};
            float ar[8] = {a0.x, a0.y, a0.z, a0.w, a1.x, a1.y, a1.z, a1.w};
#pragma unroll
            for (int r = 0; r < 8; r++) {
                u64 ab = pack2(ar[r], ar[r]);
#pragma unroll
                for (int cp = 0; cp < 4; cp++) acc[r][cp] = fma2(ab, bp[cp], acc[r][cp]);
            }
        }
    }
    __syncthreads();

#pragma unroll
    for (int r = 0; r < 8; r++) {
        int row = ty * 8 + r;
        float rs = s_rs[row];
#pragma unroll
        for (int cp = 0; cp < 4; cp++) {
            float x, y;
            unpack2(acc[r][cp], x, y);
            int c0 = tx * 8 + 2 * cp;
            x = fmaxf(x + s_b1[c0], 0.f) * rs;
            y = fmaxf(y + s_b1[c0 + 1], 0.f) * rs;
            sH[(c0) * 132 + row]     = x;
            sH[(c0 + 1) * 132 + row] = y;
        }
    }

    u64 acc2[8][2];
#pragma unroll
    for (int r = 0; r < 8; r++) { acc2[r][0] = 0ull; acc2[r][1] = 0ull; }

    for (int kc = 0; kc < 4; kc++) {
        __syncthreads();
        {
            int idx = tid;                          // float4 idx, 512 total
#pragma unroll
            for (int it = 0; it < 2; it++, idx += 256) {
                int k = idx >> 4, c4 = (idx & 15) * 4;
                int kr = kc * 32 + k;
                float4 v;
                if (c4 < 32) v = *(const float4*)&W2[kr * 32 + c4];
                else         v = *(const float4*)&W3[kr * 32 + (c4 - 32)];
                *(float4*)&sW[k * 64 + c4] = v;
            }
        }
        __syncthreads();
#pragma unroll 4
        for (int k = 0; k < 32; k++) {
            const float* Ak = &sH[(kc * 32 + k) * 132];
            const float* Wk = &sW[k * 64];
            float4 a0 = *(const float4*)&Ak[ty * 8];
            float4 a1 = *(const float4*)&Ak[ty * 8 + 4];
            float4 w0 = *(const float4*)&Wk[tx * 4];
            u64 bp[2] = {pack2(w0.x, w0.y), pack2(w0.z, w0.w)};
            float ar[8] = {a0.x, a0.y, a0.z, a0.w, a1.x, a1.y, a1.z, a1.w};
#pragma unroll
            for (int r = 0; r < 8; r++) {
                u64 ab = pack2(ar[r], ar[r]);
                acc2[r][0] = fma2(ab, bp[0], acc2[r][0]);
                acc2[r][1] = fma2(ab, bp[1], acc2[r][1]);
            }
        }
    }
#pragma unroll
    for (int r = 0; r < 8; r++) {
        float v[4];
        unpack2(acc2[r][0], v[0], v[1]);
        unpack2(acc2[r][1], v[2], v[3]);
        *(float4*)&g_p[(size_t)(n0 + ty * 8 + r) * 64 + tx * 4] =
            make_float4(v[0], v[1], v[2], v[3]);
    }
}

// ---------------- adj = sigmoid(Z Z^T): upper-tri + mirror -----------------
__global__ __launch_bounds__(256, 2) void k_adj(float* __restrict__ out) {
    __shared__ __align__(16) float sA[32 * 132];
    __shared__ __align__(16) float sB[32 * 132];

    int g = blockIdx.y;
    int t = blockIdx.x, bi = 0;
    while (t >= 8 - bi) { t -= 8 - bi; bi++; }
    int bj = bi + t;
    int i0 = bi * 128, j0 = bj * 128;

    const float4* zA4 = (const float4*)(g_z + ((size_t)(g * NPG + i0)) * OUTF);
    const float4* zB4 = (const float4*)(g_z + ((size_t)(g * NPG + j0)) * OUTF);
    int tid = threadIdx.x;

#pragma unroll
    for (int it = 0; it < 4; it++) {
        int idx = it * 256 + tid;                  // float4 idx, 1024 total
        int r = idx >> 3, k4 = (idx & 7) * 4;
        float4 va = zA4[idx];
        float4 vb = zB4[idx];
        sA[(k4 + 0) * 132 + r] = va.x;
        sA[(k4 + 1) * 132 + r] = va.y;
        sA[(k4 + 2) * 132 + r] = va.z;
        sA[(k4 + 3) * 132 + r] = va.w;
        sB[(k4 + 0) * 132 + r] = vb.x;
        sB[(k4 + 1) * 132 + r] = vb.y;
        sB[(k4 + 2) * 132 + r] = vb.z;
        sB[(k4 + 3) * 132 + r] = vb.w;
    }
    __syncthreads();

    int tx = tid & 15, ty = tid >> 4;
    u64 acc[4][8];
#pragma unroll
    for (int rp = 0; rp < 4; rp++)
#pragma unroll
        for (int c = 0; c < 8; c++) acc[rp][c] = 0ull;

#pragma unroll 4
    for (int k = 0; k < 32; k++) {
        const ulonglong2* Ap = (const ulonglong2*)&sA[k * 132 + ty * 8];
        ulonglong2 a01 = Ap[0], a23 = Ap[1];
        u64 ap[4] = {a01.x, a01.y, a23.x, a23.y};
        const float4* Bp = (const float4*)&sB[k * 132 + tx * 8];
        float4 b0 = Bp[0], b1 = Bp[1];
        u64 bp[8] = {pack2(b0.x, b0.x), pack2(b0.y, b0.y),
                     pack2(b0.z, b0.z), pack2(b0.w, b0.w),
                     pack2(b1.x, b1.x), pack2(b1.y, b1.y),
                     pack2(b1.z, b1.z), pack2(b1.w, b1.w)};
#pragma unroll
        for (int rp = 0; rp < 4; rp++)
#pragma unroll
            for (int c = 0; c < 8; c++) acc[rp][c] = fma2(ap[rp], bp[c], acc[rp][c]);
    }

    float m[8][8];
#pragma unroll
    for (int rp = 0; rp < 4; rp++)
#pragma unroll
        for (int c = 0; c < 8; c++) {
            float x, y;
            unpack2(acc[rp][c], x, y);
            m[2 * rp][c]     = sigm(x);
            m[2 * rp + 1][c] = sigm(y);
        }

    float* ob = out + ((size_t)(g * NPG + i0)) * NPG + j0;
#pragma unroll
    for (int r = 0; r < 8; r++) {
        float* o = &ob[(size_t)(ty * 8 + r) * NPG + tx * 8];
        *(float4*)&o[0] = make_float4(m[r][0], m[r][1], m[r][2], m[r][3]);
        *(float4*)&o[4] = make_float4(m[r][4], m[r][5], m[r][6], m[r][7]);
    }
    if (bi != bj) {
        float* obT = out + ((size_t)(g * NPG + j0)) * NPG + i0;
#pragma unroll
        for (int c = 0; c < 8; c++) {
            float* o = &obT[(size_t)(tx * 8 + c) * NPG + ty * 8];
            *(float4*)&o[0] = make_float4(m[0][c], m[1][c], m[2][c], m[3][c]);
            *(float4*)&o[4] = make_float4(m[4][c], m[5][c], m[6][c], m[7][c]);
        }
    }
}

// ---------------- launch ---------------------------------------------------
extern "C" void kernel_launch(void* const* d_in, const int* in_sizes, int n_in,
                              void* d_out, int out_size) {
    const float* features = (const float*)d_in[0];
    const int*   src      = (const int*)d_in[1];
    const int*   dst      = (const int*)d_in[2];
    const float* noise    = (const float*)d_in[3];
    const float* W1       = (const float*)d_in[4];
    const float* b1       = (const float*)d_in[5];
    const float* W2       = (const float*)d_in[6];
    const float* b2       = (const float*)d_in[7];
    const float* W3       = (const float*)d_in[8];
    const float* b3       = (const float*)d_in[9];

    float* out      = (float*)d_out;
    float* out_adj  = out;
    float* out_mean = out + MEAN_OFF;
    float* out_ls   = out + LS_OFF;

    static int smem_set = 0;
    if (!smem_set) {
        cudaFuncSetAttribute(k_agg1s, cudaFuncAttributeMaxDynamicSharedMemorySize, AGG_SMEM);
        cudaFuncSetAttribute(k_agg2s, cudaFuncAttributeMaxDynamicSharedMemorySize, AGG_SMEM);
        cudaFuncSetAttribute(k_mlp,   cudaFuncAttributeMaxDynamicSharedMemorySize, MLP_SMEM);
        smem_set = 1;
    }

    k_build<<<BB, 1024>>>(src, dst);
    k_agg1s<<<dim3(BB, 2), 1024, AGG_SMEM>>>(features);
    k_mlp<<<512, 256, MLP_SMEM>>>(W1, b1, W2, W3);
    k_agg2s<<<dim3(BB, 2), 1024, AGG_SMEM>>>();
    k_z<<<NN * 32 / 256, 256>>>(noise, b2, b3, out_mean, out_ls);
    k_adj<<<dim3(36, BB), 256>>>(out_adj);
}

// round 12
// speedup vs baseline: 1.3182x; 1.1517x over previous
#include <cuda_runtime.h>
#include <math.h>

#define BB   64
#define NPG  1024
#define NN   (BB * NPG)       // 65536 nodes
#define EE   (BB * 16384)     // 1048576 edges
#define EPG  16384            // edges per graph
#define EPG2 20480            // padded csr stride per graph
#define INF  64
#define HIDF 128
#define OUTF 32

#define DUMMY_OFF (1024 * 128)   // byte offset of the zero row in s_f

#define ADJ_ELEMS  ((size_t)BB * NPG * NPG)   // 67108864
#define MEAN_OFF   ADJ_ELEMS
#define LS_OFF     (ADJ_ELEMS + (size_t)NN * OUTF)

#define AGG_SMEM   (1025 * 32 * 4 + EPG2 * 4)   // 213120 B
#define MLP_SMEM   ((128 * 132 + 32 * 132 + 32 * 128 + 256) * 4)   // 101888 B

// ---------------- scratch (static device globals; no runtime alloc) -------
__device__ float g_rs_out[NN];
__device__ float g_rs_in[NN];
__device__ int   g_rp2[BB * (NPG + 1)];   // per-graph padded rowptr (local)
__device__ int   g_csr[BB * EPG2];        // pre-scaled LOCAL byte offsets
__device__ float g_a[NN * INF];
__device__ float g_p[NN * 64];
__device__ float g_q[NN * 64];
__device__ float g_z[NN * OUTF];

typedef unsigned long long u64;

// ---------------- f32x2 helpers (FFMA2) -----------------------------------
__device__ __forceinline__ u64 pack2(float lo, float hi) {
    u64 r;
    asm("mov.b64 %0, {%1, %2};" : "=l"(r) : "f"(lo), "f"(hi));
    return r;
}
__device__ __forceinline__ u64 fma2(u64 a, u64 b, u64 c) {
    u64 d;
    asm("fma.rn.f32x2 %0, %1, %2, %3;" : "=l"(d) : "l"(a), "l"(b), "l"(c));
    return d;
}
__device__ __forceinline__ void unpack2(u64 v, float& a, float& b) {
    asm("mov.b64 {%0, %1}, %2;" : "=f"(a), "=f"(b) : "l"(v));
}
// sigmoid via single-MUFU tanh: sigma(x) = 0.5*tanh(0.5x) + 0.5
__device__ __forceinline__ float sigm(float x) {
    float t;
    float h = 0.5f * x;
    asm("tanh.approx.f32 %0, %1;" : "=f"(t) : "f"(h));
    return fmaf(0.5f, t, 0.5f);
}

// ---------------- k_build: per-graph padded CSR ----------------------------
__global__ __launch_bounds__(1024) void k_build(const int* __restrict__ src,
                                                const int* __restrict__ dst) {
    __shared__ int s_cin[NPG];
    __shared__ int s_cout[NPG];
    __shared__ int s_scan[NPG];
    __shared__ int s_fill[NPG];
    int g = blockIdx.x, t = threadIdx.x;
    int base_n = g * NPG, base_e = g * EPG;
    int base_e2 = g * EPG2;

    s_cin[t] = 0; s_cout[t] = 0;
    __syncthreads();
#pragma unroll
    for (int it = 0; it < 16; it++) {
        int e = base_e + it * 1024 + t;
        atomicAdd(&s_cin[dst[e] - base_n], 1);
        atomicAdd(&s_cout[src[e] - base_n], 1);
    }
    __syncthreads();
    int v  = s_cin[t];
    int vp = (v + 3) & ~3;
    s_scan[t] = vp;
    __syncthreads();
    for (int ofs = 1; ofs < 1024; ofs <<= 1) {
        int x = (t >= ofs) ? s_scan[t - ofs] : 0;
        __syncthreads();
        s_scan[t] += x;
        __syncthreads();
    }
    int excl = s_scan[t] - vp;
    g_rp2[g * (NPG + 1) + t] = excl;
    if (t == 1023) g_rp2[g * (NPG + 1) + 1024] = excl + vp;
    g_rs_in[base_n + t]  = rsqrtf((float)max(v, 1));
    g_rs_out[base_n + t] = rsqrtf((float)max(s_cout[t], 1));
    s_fill[t] = excl;
    __syncthreads();
#pragma unroll
    for (int it = 0; it < 16; it++) {
        int e = base_e + it * 1024 + t;
        int d = dst[e] - base_n;
        int pos = atomicAdd(&s_fill[d], 1);
        g_csr[base_e2 + pos] = (src[e] - base_n) * 128;
    }
    for (int j = excl + v; j < excl + vp; j++)
        g_csr[base_e2 + j] = DUMMY_OFF;
}

// ---------------- branch-free gather over padded int4 groups --------------
__device__ __forceinline__ float gather_sum(const int* __restrict__ s_csr,
                                            const char* __restrict__ fb,
                                            int beg, int end) {
    float a = 0.f;
#pragma unroll 2
    for (int e = beg; e < end; e += 4) {
        int4 o = *(const int4*)&s_csr[e];
        a += (*(const float*)(fb + o.x) + *(const float*)(fb + o.y)) +
             (*(const float*)(fb + o.z) + *(const float*)(fb + o.w));
    }
    return a;
}

// ---------------- smem-staged aggregation of input features ---------------
__global__ __launch_bounds__(1024) void k_agg1s(const float* __restrict__ feat) {
    extern __shared__ __align__(16) char s_raw[];
    float* s_f = (float*)s_raw;                    // 1025*32 floats
    int* s_csr = (int*)(s_raw + 1025 * 32 * 4);    // EPG2 ints
    int g = blockIdx.x, h = blockIdx.y;
    int base_n = g * NPG;
    int t = threadIdx.x;

#pragma unroll
    for (int it = 0; it < 8; it++) {
        int idx = it * 1024 + t;
        int row = idx >> 3, q = idx & 7;
        float rs = g_rs_out[base_n + row];
        float4 v = *(const float4*)&feat[(size_t)(base_n + row) * INF + h * 32 + q * 4];
        v.x *= rs; v.y *= rs; v.z *= rs; v.w *= rs;
        *(float4*)&s_f[row * 32 + q * 4] = v;
    }
    if (t < 8) *(float4*)&s_f[1024 * 32 + t * 4] = make_float4(0.f, 0.f, 0.f, 0.f);
#pragma unroll
    for (int it = 0; it < 5; it++) {
        ((int4*)s_csr)[it * 1024 + t] = ((const int4*)(g_csr + g * EPG2))[it * 1024 + t];
    }

    int warp = t >> 5, lane = t & 31;
    const int* rp = &g_rp2[g * (NPG + 1) + warp * 32];
    int rpA = rp[lane];
    int rpB = rp[lane + 1];
    float rinv = g_rs_in[base_n + warp * 32 + lane];
    __syncthreads();

    const char* fb = (const char*)s_f + lane * 4;
    float* outp = &g_a[(size_t)(base_n + warp * 32) * INF + h * 32 + lane];
#pragma unroll 1
    for (int i = 0; i < 32; i++) {
        int beg = __shfl_sync(0xffffffffu, rpA, i);
        int end = __shfl_sync(0xffffffffu, rpB, i);
        float rin = __shfl_sync(0xffffffffu, rinv, i);
        float a = gather_sum(s_csr, fb, beg, end);
        outp[(size_t)i * INF] = a * rin;
    }
}

// ---------------- smem-staged aggregation of p -> q -----------------------
__global__ __launch_bounds__(1024) void k_agg2s() {
    extern __shared__ __align__(16) char s_raw[];
    float* s_f = (float*)s_raw;
    int* s_csr = (int*)(s_raw + 1025 * 32 * 4);
    int g = blockIdx.x, h = blockIdx.y;
    int base_n = g * NPG;
    int t = threadIdx.x;

#pragma unroll
    for (int it = 0; it < 8; it++) {
        int idx = it * 1024 + t;
        int row = idx >> 3, q = idx & 7;
        float4 v = *(const float4*)&g_p[(size_t)(base_n + row) * 64 + h * 32 + q * 4];
        *(float4*)&s_f[row * 32 + q * 4] = v;
    }
    if (t < 8) *(float4*)&s_f[1024 * 32 + t * 4] = make_float4(0.f, 0.f, 0.f, 0.f);
#pragma unroll
    for (int it = 0; it < 5; it++) {
        ((int4*)s_csr)[it * 1024 + t] = ((const int4*)(g_csr + g * EPG2))[it * 1024 + t];
    }

    int warp = t >> 5, lane = t & 31;
    const int* rp = &g_rp2[g * (NPG + 1) + warp * 32];
    int rpA = rp[lane];
    int rpB = rp[lane + 1];
    float rinv = g_rs_in[base_n + warp * 32 + lane];
    __syncthreads();

    const char* fb = (const char*)s_f + lane * 4;
    float* outp = &g_q[(size_t)(base_n + warp * 32) * 64 + h * 32 + lane];
#pragma unroll 1
    for (int i = 0; i < 32; i++) {
        int beg = __shfl_sync(0xffffffffu, rpA, i);
        int end = __shfl_sync(0xffffffffu, rpB, i);
        float rin = __shfl_sync(0xffffffffu, rinv, i);
        float a = gather_sum(s_csr, fb, beg, end);
        outp[(size_t)i * 64] = a * rin;
    }
}

// ---------------- z epilogue: mean/ls/z from q ----------------------------
__global__ __launch_bounds__(256) void k_z(const float* __restrict__ noise,
                                           const float* __restrict__ b2,
                                           const float* __restrict__ b3,
                                           float* __restrict__ out_mean,
                                           float* __restrict__ out_ls) {
    int idx = blockIdx.x * 256 + threadIdx.x;
    int n = idx >> 5, l = idx & 31;
    float mean = g_q[(size_t)n * 64 + l] + b2[l];
    float ls   = g_q[(size_t)n * 64 + 32 + l] + b3[l];
    float z    = fmaf(noise[idx], __expf(ls), mean);
    out_mean[idx] = mean;
    out_ls[idx]   = ls;
    g_z[idx]      = z;
}

// ---------------- fused MLP: h=relu(aW1+b1); p=(h*rs)@[W2|W3] -------------
// stage1 cols split tx*4 and 64+tx*4 (conflict-free 16B lane stride)
__global__ __launch_bounds__(256, 2) void k_mlp(const float* __restrict__ W1,
                                                const float* __restrict__ b1,
                                                const float* __restrict__ W2,
                                                const float* __restrict__ W3) {
    extern __shared__ __align__(16) char s_raw[];
    float* sH   = (float*)s_raw;               // 128*132 : h^T scaled
    float* sA   = sH + 128 * 132;              // 32*132
    float* sW   = sA + 32 * 132;               // 32*128 / 32*64
    float* s_rs = sW + 32 * 128;               // 128
    float* s_b1 = s_rs + 128;                  // 128

    int tid = threadIdx.x;
    int n0 = blockIdx.x * 128;
    if (tid < 128) {
        s_rs[tid] = g_rs_out[n0 + tid];
        s_b1[tid] = b1[tid];
    }
    int tx = tid & 15, ty = tid >> 4;

    u64 acc[8][4];
#pragma unroll
    for (int r = 0; r < 8; r++)
#pragma unroll
        for (int cp = 0; cp < 4; cp++) acc[r][cp] = 0ull;

    for (int kc = 0; kc < 2; kc++) {
        __syncthreads();
#pragma unroll
        for (int it = 0; it < 4; it++) {
            int idx = it * 256 + tid;
            int r = idx >> 3, k4 = (idx & 7) * 4;
            float4 v = *(const float4*)&g_a[(size_t)(n0 + r) * INF + kc * 32 + k4];
            sA[(k4 + 0) * 132 + r] = v.x;
            sA[(k4 + 1) * 132 + r] = v.y;
            sA[(k4 + 2) * 132 + r] = v.z;
            sA[(k4 + 3) * 132 + r] = v.w;
        }
#pragma unroll
        for (int it = 0; it < 4; it++) {
            int idx = it * 256 + tid;
            ((float4*)sW)[idx] = ((const float4*)(W1 + kc * 32 * 128))[idx];
        }
        __syncthreads();
#pragma unroll 4
        for (int k = 0; k < 32; k++) {
            const float* Ak = &sA[k * 132];
            const float* Wk = &sW[k * 128];
            float4 a0 = *(const float4*)&Ak[ty * 8];
            float4 a1 = *(const float4*)&Ak[ty * 8 + 4];
            float4 w0 = *(const float4*)&Wk[tx * 4];          // cols tx*4..+3
            float4 w1 = *(const float4*)&Wk[64 + tx * 4];     // cols 64+tx*4..+3
            u64 bp[4] = {pack2(w0.x, w0.y), pack2(w0.z, w0.w),
                         pack2(w1.x, w1.y), pack2(w1.z, w1.w)};
            float ar[8] = {a0.x, a0.y, a0.z, a0.w, a1.x, a1.y, a1.z, a1.w};
#pragma unroll
            for (int r = 0; r < 8; r++) {
                u64 ab = pack2(ar[r], ar[r]);
#pragma unroll
                for (int cp = 0; cp < 4; cp++) acc[r][cp] = fma2(ab, bp[cp], acc[r][cp]);
            }
        }
    }
    __syncthreads();

#pragma unroll
    for (int r = 0; r < 8; r++) {
        int row = ty * 8 + r;
        float rs = s_rs[row];
#pragma unroll
        for (int cp = 0; cp < 4; cp++) {
            float x, y;
            unpack2(acc[r][cp], x, y);
            int c0 = (cp < 2) ? (tx * 4 + 2 * cp) : (64 + tx * 4 + 2 * (cp - 2));
            x = fmaxf(x + s_b1[c0], 0.f) * rs;
            y = fmaxf(y + s_b1[c0 + 1], 0.f) * rs;
            sH[(c0) * 132 + row]     = x;
            sH[(c0 + 1) * 132 + row] = y;
        }
    }

    u64 acc2[8][2];
#pragma unroll
    for (int r = 0; r < 8; r++) { acc2[r][0] = 0ull; acc2[r][1] = 0ull; }

    for (int kc = 0; kc < 4; kc++) {
        __syncthreads();
        {
            int idx = tid;
#pragma unroll
            for (int it = 0; it < 2; it++, idx += 256) {
                int k = idx >> 4, c4 = (idx & 15) * 4;
                int kr = kc * 32 + k;
                float4 v;
                if (c4 < 32) v = *(const float4*)&W2[kr * 32 + c4];
                else         v = *(const float4*)&W3[kr * 32 + (c4 - 32)];
                *(float4*)&sW[k * 64 + c4] = v;
            }
        }
        __syncthreads();
#pragma unroll 4
        for (int k = 0; k < 32; k++) {
            const float* Ak = &sH[(kc * 32 + k) * 132];
            const float* Wk = &sW[k * 64];
            float4 a0 = *(const float4*)&Ak[ty * 8];
            float4 a1 = *(const float4*)&Ak[ty * 8 + 4];
            float4 w0 = *(const float4*)&Wk[tx * 4];
            u64 bp[2] = {pack2(w0.x, w0.y), pack2(w0.z, w0.w)};
            float ar[8] = {a0.x, a0.y, a0.z, a0.w, a1.x, a1.y, a1.z, a1.w};
#pragma unroll
            for (int r = 0; r < 8; r++) {
                u64 ab = pack2(ar[r], ar[r]);
                acc2[r][0] = fma2(ab, bp[0], acc2[r][0]);
                acc2[r][1] = fma2(ab, bp[1], acc2[r][1]);
            }
        }
    }
#pragma unroll
    for (int r = 0; r < 8; r++) {
        float v[4];
        unpack2(acc2[r][0], v[0], v[1]);
        unpack2(acc2[r][1], v[2], v[3]);
        *(float4*)&g_p[(size_t)(n0 + ty * 8 + r) * 64 + tx * 4] =
            make_float4(v[0], v[1], v[2], v[3]);
    }
}

// ---------------- adj = sigmoid(Z Z^T): upper-tri + mirror -----------------
// cols split tx*4 / 64+tx*4 -> conflict-free B loads & stores
__global__ __launch_bounds__(256, 2) void k_adj(float* __restrict__ out) {
    __shared__ __align__(16) float sA[32 * 132];
    __shared__ __align__(16) float sB[32 * 132];

    int g = blockIdx.y;
    int t = blockIdx.x, bi = 0;
    while (t >= 8 - bi) { t -= 8 - bi; bi++; }
    int bj = bi + t;
    int i0 = bi * 128, j0 = bj * 128;

    const float4* zA4 = (const float4*)(g_z + ((size_t)(g * NPG + i0)) * OUTF);
    const float4* zB4 = (const float4*)(g_z + ((size_t)(g * NPG + j0)) * OUTF);
    int tid = threadIdx.x;

#pragma unroll
    for (int it = 0; it < 4; it++) {
        int idx = it * 256 + tid;
        int r = idx >> 3, k4 = (idx & 7) * 4;
        float4 va = zA4[idx];
        float4 vb = zB4[idx];
        sA[(k4 + 0) * 132 + r] = va.x;
        sA[(k4 + 1) * 132 + r] = va.y;
        sA[(k4 + 2) * 132 + r] = va.z;
        sA[(k4 + 3) * 132 + r] = va.w;
        sB[(k4 + 0) * 132 + r] = vb.x;
        sB[(k4 + 1) * 132 + r] = vb.y;
        sB[(k4 + 2) * 132 + r] = vb.z;
        sB[(k4 + 3) * 132 + r] = vb.w;
    }
    __syncthreads();

    int tx = tid & 15, ty = tid >> 4;
    // acc[rp][c]: rows (ty*8+2rp, +1); cols c<4 -> tx*4+c, c>=4 -> 64+tx*4+c-4
    u64 acc[4][8];
#pragma unroll
    for (int rp = 0; rp < 4; rp++)
#pragma unroll
        for (int c = 0; c < 8; c++) acc[rp][c] = 0ull;

#pragma unroll 4
    for (int k = 0; k < 32; k++) {
        const ulonglong2* Ap = (const ulonglong2*)&sA[k * 132 + ty * 8];
        ulonglong2 a01 = Ap[0], a23 = Ap[1];
        u64 ap[4] = {a01.x, a01.y, a23.x, a23.y};
        float4 b0 = *(const float4*)&sB[k * 132 + tx * 4];
        float4 b1 = *(const float4*)&sB[k * 132 + 64 + tx * 4];
        u64 bp[8] = {pack2(b0.x, b0.x), pack2(b0.y, b0.y),
                     pack2(b0.z, b0.z), pack2(b0.w, b0.w),
                     pack2(b1.x, b1.x), pack2(b1.y, b1.y),
                     pack2(b1.z, b1.z), pack2(b1.w, b1.w)};
#pragma unroll
        for (int rp = 0; rp < 4; rp++)
#pragma unroll
            for (int c = 0; c < 8; c++) acc[rp][c] = fma2(ap[rp], bp[c], acc[rp][c]);
    }

    float m[8][8];
#pragma unroll
    for (int rp = 0; rp < 4; rp++)
#pragma unroll
        for (int c = 0; c < 8; c++) {
            float x, y;
            unpack2(acc[rp][c], x, y);
            m[2 * rp][c]     = sigm(x);
            m[2 * rp + 1][c] = sigm(y);
        }

    float* ob = out + ((size_t)(g * NPG + i0)) * NPG + j0;
#pragma unroll
    for (int r = 0; r < 8; r++) {
        float* o = &ob[(size_t)(ty * 8 + r) * NPG];
        *(float4*)&o[tx * 4]      = make_float4(m[r][0], m[r][1], m[r][2], m[r][3]);
        *(float4*)&o[64 + tx * 4] = make_float4(m[r][4], m[r][5], m[r][6], m[r][7]);
    }
    if (bi != bj) {
        float* obT = out + ((size_t)(g * NPG + j0)) * NPG + i0;
#pragma unroll
        for (int c = 0; c < 8; c++) {
            int jcol = (c < 4) ? (tx * 4 + c) : (64 + tx * 4 + c - 4);
            float* o = &obT[(size_t)jcol * NPG + ty * 8];
            *(float4*)&o[0] = make_float4(m[0][c], m[1][c], m[2][c], m[3][c]);
            *(float4*)&o[4] = make_float4(m[4][c], m[5][c], m[6][c], m[7][c]);
        }
    }
}

// ---------------- launch ---------------------------------------------------
extern "C" void kernel_launch(void* const* d_in, const int* in_sizes, int n_in,
                              void* d_out, int out_size) {
    const float* features = (const float*)d_in[0];
    const int*   src      = (const int*)d_in[1];
    const int*   dst      = (const int*)d_in[2];
    const float* noise    = (const float*)d_in[3];
    const float* W1       = (const float*)d_in[4];
    const float* b1       = (const float*)d_in[5];
    const float* W2       = (const float*)d_in[6];
    const float* b2       = (const float*)d_in[7];
    const float* W3       = (const float*)d_in[8];
    const float* b3       = (const float*)d_in[9];

    float* out      = (float*)d_out;
    float* out_adj  = out;
    float* out_mean = out + MEAN_OFF;
    float* out_ls   = out + LS_OFF;

    static int smem_set = 0;
    if (!smem_set) {
        cudaFuncSetAttribute(k_agg1s, cudaFuncAttributeMaxDynamicSharedMemorySize, AGG_SMEM);
        cudaFuncSetAttribute(k_agg2s, cudaFuncAttributeMaxDynamicSharedMemorySize, AGG_SMEM);
        cudaFuncSetAttribute(k_mlp,   cudaFuncAttributeMaxDynamicSharedMemorySize, MLP_SMEM);
        smem_set = 1;
    }

    k_build<<<BB, 1024>>>(src, dst);
    k_agg1s<<<dim3(BB, 2), 1024, AGG_SMEM>>>(features);
    k_mlp<<<512, 256, MLP_SMEM>>>(W1, b1, W2, W3);
    k_agg2s<<<dim3(BB, 2), 1024, AGG_SMEM>>>();
    k_z<<<NN * 32 / 256, 256>>>(noise, b2, b3, out_mean, out_ls);
    k_adj<<<dim3(36, BB), 256>>>(out_adj);
}